// round 2
// baseline (speedup 1.0000x reference)
#include <cuda_runtime.h>
#include <cuda_bf16.h>

// Problem constants (fixed shapes from reference setup_inputs)
#define BB 2048
#define NN 8192
#define LL 512
#define NEGBIG (-1e30f)

// Per-row scratch (allocation-free: __device__ globals)
__device__ float g_row_ll[BB];
__device__ int   g_row_used[BB];

// One block (128 threads) per row; 4 elements per thread (L=512).
// Indices are int32 (JAX default x64-disabled: astype(int64) is a no-op).
__global__ __launch_bounds__(128) void listnet_row_kernel(
    const float* __restrict__ s, const int* __restrict__ seqs)
{
    const int b    = blockIdx.x;
    const int t    = threadIdx.x;
    const int lane = t & 31;
    const int warp = t >> 5;

    const float* __restrict__ srow = s + (size_t)b * NN;

    // Coalesced 16B vector load of 4 int32 indices
    const int4 vi = *(const int4*)(seqs + (size_t)b * LL + t * 4);
    int v[4] = {vi.x, vi.y, vi.z, vi.w};

    float g[4], gm[4];
    bool  mk[4];
#pragma unroll
    for (int j = 0; j < 4; j++) {
        int vv = v[j];
        mk[j] = (vv != -1);
        int idx = vv < 0 ? 0 : (vv > (NN - 1) ? (NN - 1) : vv);
        float x = __ldg(srow + idx);        // random-access gather (L2-resident)
        // sanitize: nan->0, +inf->1e6, -inf->-1e6
        if (isnan(x))       x = 0.0f;
        else if (isinf(x))  x = (x > 0.0f) ? 1e6f : -1e6f;
        g[j]  = x;
        gm[j] = mk[j] ? x : NEGBIG;
    }

    // ---- block max of gm (global max M for the row) ----
    float mx = fmaxf(fmaxf(gm[0], gm[1]), fmaxf(gm[2], gm[3]));
#pragma unroll
    for (int off = 16; off; off >>= 1)
        mx = fmaxf(mx, __shfl_xor_sync(0xffffffffu, mx, off));
    __shared__ float smax[4];
    __shared__ float swsum[4];
    if (lane == 0) smax[warp] = mx;
    __syncthreads();
    const float M = fmaxf(fmaxf(smax[0], smax[1]), fmaxf(smax[2], smax[3]));

    // ---- exp once per element (masked entries -> exp(-huge) = 0) ----
    float e[4];
#pragma unroll
    for (int j = 0; j < 4; j++) e[j] = __expf(gm[j] - M);

    // ---- suffix (reverse) sum scan of exp values across the block ----
    float csum = (e[0] + e[1]) + (e[2] + e[3]);   // per-thread chunk total
    float incl = csum;                             // inclusive suffix within warp
#pragma unroll
    for (int off = 1; off < 32; off <<= 1) {
        float o = __shfl_down_sync(0xffffffffu, incl, off);
        if (lane + off < 32) incl += o;
    }
    if (lane == 0) swsum[warp] = incl;             // warp totals
    __syncthreads();
    float after = 0.0f;
    for (int w = warp + 1; w < 4; w++) after += swsum[w];
    float exclw = __shfl_down_sync(0xffffffffu, incl, 1);  // exclusive within warp
    float acc = ((lane < 31) ? exclw : 0.0f) + after;

    // ---- per-element log_den + masked NLL accumulation (right-to-left) ----
    float ll = 0.0f;
#pragma unroll
    for (int j = 3; j >= 0; j--) {
        acc += e[j];                               // suffix sum incl. element j
        if (mk[j]) ll += g[j] - (M + __logf(acc)); // log_den = M + log(sum)
    }

    // ---- block reduce ll + "row used" flag ----
    bool any = mk[0] || mk[1] || mk[2] || mk[3];
    unsigned anyb = __ballot_sync(0xffffffffu, any);
#pragma unroll
    for (int off = 16; off; off >>= 1)
        ll += __shfl_xor_sync(0xffffffffu, ll, off);
    __shared__ float    sll[4];
    __shared__ unsigned sany[4];
    if (lane == 0) { sll[warp] = ll; sany[warp] = anyb; }
    __syncthreads();
    if (t == 0) {
        g_row_ll[b]   = (sll[0] + sll[1]) + (sll[2] + sll[3]);
        g_row_used[b] = ((sany[0] | sany[1] | sany[2] | sany[3]) != 0u) ? 1 : 0;
    }
}

// Deterministic single-block tree reduction -> scalar loss
__global__ __launch_bounds__(1024) void listnet_reduce_kernel(float* __restrict__ out)
{
    const int t = threadIdx.x;
    float sum = 0.0f;
    int   cnt = 0;
#pragma unroll
    for (int i = t; i < BB; i += 1024) {
        if (g_row_used[i]) { sum += g_row_ll[i]; cnt++; }
    }
    __shared__ float sb[1024];
    __shared__ int   cb[1024];
    sb[t] = sum; cb[t] = cnt;
    __syncthreads();
    for (int sft = 512; sft > 0; sft >>= 1) {
        if (t < sft) { sb[t] += sb[t + sft]; cb[t] += cb[t + sft]; }
        __syncthreads();
    }
    if (t == 0) out[0] = (cb[0] > 0) ? (-sb[0] / (float)cb[0]) : 0.0f;
}

extern "C" void kernel_launch(void* const* d_in, const int* in_sizes, int n_in,
                              void* d_out, int out_size)
{
    const float* s    = (const float*)d_in[0];   // [B, N] float32
    const int*   seqs = (const int*)d_in[1];     // [B, L] int32 (JAX x64 off)
    float*       out  = (float*)d_out;           // [1] float32

    listnet_row_kernel<<<BB, 128>>>(s, seqs);
    listnet_reduce_kernel<<<1, 1024>>>(out);
}

// round 3
// speedup vs baseline: 1.0127x; 1.0127x over previous
#include <cuda_runtime.h>
#include <cuda_bf16.h>

// Problem constants (fixed shapes from reference setup_inputs)
#define BB 2048
#define NN 8192
#define LL 512
#define NEGBIG (-1e30f)

// Per-row scratch + completion counter (allocation-free: __device__ globals)
__device__ float        g_row_ll[BB];
__device__ unsigned     g_row_used[BB];
__device__ unsigned int g_done_count = 0;   // returns to 0 at end of every launch

// One block (128 threads) per row; 4 elements per thread (L=512).
// Last-arriving block performs the deterministic final reduction.
__global__ __launch_bounds__(128) void listnet_fused_kernel(
    const float* __restrict__ s, const int* __restrict__ seqs,
    float* __restrict__ out)
{
    const int b    = blockIdx.x;
    const int t    = threadIdx.x;
    const int lane = t & 31;
    const int warp = t >> 5;

    const float* __restrict__ srow = s + (size_t)b * NN;

    // Coalesced 16B vector load of 4 int32 indices
    const int4 vi = *(const int4*)(seqs + (size_t)b * LL + t * 4);
    int v[4] = {vi.x, vi.y, vi.z, vi.w};

    float g[4], e[4];
    bool  mk[4];
#pragma unroll
    for (int j = 0; j < 4; j++) {
        int vv = v[j];
        mk[j] = (vv != -1);
        int idx = vv < 0 ? 0 : (vv > (NN - 1) ? (NN - 1) : vv);
        float x = __ldg(srow + idx);            // random-access gather (L2-resident)
        // branchless sanitize: inf -> +/-1e6 via clamp, nan -> 0
        x = fminf(fmaxf(x, -1e6f), 1e6f);       // fmin/fmax also squash inf
        x = (x != x) ? 0.0f : x;                // nan -> 0 (clamp of nan is nan-free on some paths; be explicit)
        g[j] = x;
    }

    // ---- block max over valid entries ----
    float mx = NEGBIG;
#pragma unroll
    for (int j = 0; j < 4; j++) mx = fmaxf(mx, mk[j] ? g[j] : NEGBIG);
#pragma unroll
    for (int off = 16; off; off >>= 1)
        mx = fmaxf(mx, __shfl_xor_sync(0xffffffffu, mx, off));
    __shared__ float smax[4];
    __shared__ float swsum[4];
    if (lane == 0) smax[warp] = mx;
    __syncthreads();
    const float M = fmaxf(fmaxf(smax[0], smax[1]), fmaxf(smax[2], smax[3]));

    // ---- exp once per valid element (masked -> 0, MUFU predicated off) ----
#pragma unroll
    for (int j = 0; j < 4; j++) e[j] = mk[j] ? __expf(g[j] - M) : 0.0f;

    // ---- suffix (reverse) sum scan of exp values across the block ----
    float csum = (e[0] + e[1]) + (e[2] + e[3]);   // per-thread chunk total
    float incl = csum;                             // inclusive suffix within warp
#pragma unroll
    for (int off = 1; off < 32; off <<= 1) {
        float o = __shfl_down_sync(0xffffffffu, incl, off);
        if (lane + off < 32) incl += o;
    }
    if (lane == 0) swsum[warp] = incl;             // warp totals
    __syncthreads();
    float after = 0.0f;
    for (int w = warp + 1; w < 4; w++) after += swsum[w];
    float exclw = __shfl_down_sync(0xffffffffu, incl, 1);  // exclusive within warp
    float acc = ((lane < 31) ? exclw : 0.0f) + after;

    // ---- per-element log_den + masked NLL accumulation (right-to-left) ----
    float ll = 0.0f;
#pragma unroll
    for (int j = 3; j >= 0; j--) {
        acc += e[j];                               // suffix sum incl. element j
        if (mk[j]) ll += g[j] - (M + __logf(acc)); // log_den = M + log(sum)
    }

    // ---- block reduce ll + "row used" flag ----
    bool any = mk[0] || mk[1] || mk[2] || mk[3];
    unsigned anyb = __ballot_sync(0xffffffffu, any);
#pragma unroll
    for (int off = 16; off; off >>= 1)
        ll += __shfl_xor_sync(0xffffffffu, ll, off);
    __shared__ float    sll[4];
    __shared__ unsigned sany[4];
    if (lane == 0) { sll[warp] = ll; sany[warp] = anyb; }
    __syncthreads();

    __shared__ unsigned is_last;
    if (t == 0) {
        g_row_ll[b]   = (sll[0] + sll[1]) + (sll[2] + sll[3]);
        g_row_used[b] = (sany[0] | sany[1] | sany[2] | sany[3]) ? 1u : 0u;
        __threadfence();                           // publish row result
        unsigned prev = atomicAdd(&g_done_count, 1u);
        is_last = (prev == BB - 1) ? 1u : 0u;
    }
    __syncthreads();

    // ---- last block: deterministic final reduction over all rows ----
    if (is_last) {
        float sum = 0.0f;
        int   cnt = 0;
#pragma unroll
        for (int i = t; i < BB; i += 128) {        // fixed order -> deterministic
            unsigned u = __ldcg(&g_row_used[i]);   // bypass L1 (same-launch writes)
            float    r = __ldcg(&g_row_ll[i]);
            if (u) { sum += r; cnt++; }
        }
#pragma unroll
        for (int off = 16; off; off >>= 1) {
            sum += __shfl_xor_sync(0xffffffffu, sum, off);
            cnt += __shfl_xor_sync(0xffffffffu, cnt, off);
        }
        __shared__ float fsum[4];
        __shared__ int   fcnt[4];
        if (lane == 0) { fsum[warp] = sum; fcnt[warp] = cnt; }
        __syncthreads();
        if (t == 0) {
            float S = (fsum[0] + fsum[1]) + (fsum[2] + fsum[3]);
            int   C = (fcnt[0] + fcnt[1]) + (fcnt[2] + fcnt[3]);
            out[0] = (C > 0) ? (-S / (float)C) : 0.0f;
            g_done_count = 0;                      // reset for next graph replay
        }
    }
}

extern "C" void kernel_launch(void* const* d_in, const int* in_sizes, int n_in,
                              void* d_out, int out_size)
{
    const float* s    = (const float*)d_in[0];   // [B, N] float32
    const int*   seqs = (const int*)d_in[1];     // [B, L] int32 (JAX x64 off)
    float*       out  = (float*)d_out;           // [1] float32

    listnet_fused_kernel<<<BB, 128>>>(s, seqs, out);
}